// round 1
// baseline (speedup 1.0000x reference)
#include <cuda_runtime.h>

// ---------------- problem constants ----------------
#define HN   50      // hidden
#define GN   200     // 4*H gates
#define DN   8       // input dim
#define BN   2048    // batch
#define TN   512     // time steps
#define EN   16      // batch elems per CTA
#define NCTA (BN/EN) // 128
#define NTHR 256
#define EPAD 17      // padded elem-row stride for dup arrays (bank-conflict-free h writes)

typedef unsigned long long ull;

// SMEM layout (bytes):
//   ull   xdu [DN*EPAD]   = 136  ull
//   ull   h0d [HN*EPAD]   = 850  ull
//   ull   h1d [HN*EPAD]   = 850  ull
//   float Wi0t[DN*GN]     = 1600 f   ([d][g] transposed)
//   float Wh0t[HN*GN]     = 10000 f  ([k][g])
//   float Wi1t[HN*GN]     = 10000 f
//   float Wh1t[HN*GN]     = 10000 f
//   float b0  [GN], b1[GN]
//   float wl  [64]  (wlin[0..49], blin at [50])
//   float gates[EN*GN]    = 3200 f   ([e][g])
#define SMEM_ULLS   (136 + 850 + 850)
#define SMEM_FLOATS (1600 + 3*10000 + 200 + 200 + 64 + 3200)
#define SMEM_BYTES  (SMEM_ULLS*8 + SMEM_FLOATS*4)   // 155744

// ---------------- f32x2 helpers ----------------
__device__ __forceinline__ ull pack2(float a, float b) {
    ull r; asm("mov.b64 %0, {%1, %2};" : "=l"(r) : "f"(a), "f"(b)); return r;
}
__device__ __forceinline__ ull dup2(float a) { return pack2(a, a); }
__device__ __forceinline__ void fma2(ull& d, ull a, ull b) {
    asm("fma.rn.f32x2 %0, %1, %2, %0;" : "+l"(d) : "l"(a), "l"(b));
}
__device__ __forceinline__ float2 unpk2(ull v) {
    float2 f; asm("mov.b64 {%0, %1}, %2;" : "=f"(f.x), "=f"(f.y) : "l"(v)); return f;
}

__device__ __forceinline__ float sigf(float v) {
    return __fdividef(1.f, 1.f + __expf(-v));
}
__device__ __forceinline__ float tanhx(float v) {
    // tanh(v) = 2*sigmoid(2v)-1 ; safe at extremes (rcp(inf)=0)
    return fmaf(2.f, __fdividef(1.f, 1.f + __expf(-2.f * v)), -1.f);
}

// One K-block of the gate GEMM: acc[2 gate-pairs][4 elems] += Wt[k][gg4..+3] * hdup[k][eb..+3]
template<int KK, int UNROLL>
__device__ __forceinline__ void gemm_acc(const float* __restrict__ Wt,
                                         const ull*   __restrict__ hd,
                                         int gg4, int eb,
                                         ull& a00, ull& a01, ull& a02, ull& a03,
                                         ull& a10, ull& a11, ull& a12, ull& a13)
{
#pragma unroll UNROLL
    for (int k = 0; k < KK; ++k) {
        const float4 w4 = *reinterpret_cast<const float4*>(Wt + k * GN + gg4);
        const ull w01 = pack2(w4.x, w4.y);
        const ull w23 = pack2(w4.z, w4.w);
        const ull v0 = hd[k * EPAD + eb + 0];  // broadcast LDS.64 (all lanes same eb)
        const ull v1 = hd[k * EPAD + eb + 1];
        const ull v2 = hd[k * EPAD + eb + 2];
        const ull v3 = hd[k * EPAD + eb + 3];
        fma2(a00, w01, v0); fma2(a10, w23, v0);
        fma2(a01, w01, v1); fma2(a11, w23, v1);
        fma2(a02, w01, v2); fma2(a12, w23, v2);
        fma2(a03, w01, v3); fma2(a13, w23, v3);
    }
}

__global__ void __launch_bounds__(NTHR, 1)
lstm_fused_kernel(const float* __restrict__ x,
                  const float* __restrict__ Wih0, const float* __restrict__ Whh0,
                  const float* __restrict__ bih0, const float* __restrict__ bhh0,
                  const float* __restrict__ Wih1, const float* __restrict__ Whh1,
                  const float* __restrict__ bih1, const float* __restrict__ bhh1,
                  const float* __restrict__ Wlin, const float* __restrict__ blin,
                  float* __restrict__ out)
{
    extern __shared__ char smem_raw[];
    ull*   xdu  = reinterpret_cast<ull*>(smem_raw);
    ull*   h0d  = xdu + DN * EPAD;
    ull*   h1d  = h0d + HN * EPAD;
    float* fb   = reinterpret_cast<float*>(h1d + HN * EPAD);
    float* Wi0t = fb;
    float* Wh0t = Wi0t + DN * GN;
    float* Wi1t = Wh0t + HN * GN;
    float* Wh1t = Wi1t + HN * GN;
    float* b0   = Wh1t + HN * GN;
    float* b1   = b0 + GN;
    float* wl   = b1 + GN;
    float* gates= wl + 64;

    const int tid = threadIdx.x;
    const int cta = blockIdx.x;

    // ---- cooperative weight load (transpose to [k][g]) ----
    for (int i = tid; i < DN * GN; i += NTHR) {
        int g = i >> 3, d = i & 7;
        Wi0t[d * GN + g] = Wih0[i];
    }
    for (int i = tid; i < HN * GN; i += NTHR) {
        int g = i / HN, k = i - g * HN;
        Wh0t[k * GN + g] = Whh0[i];
        Wi1t[k * GN + g] = Wih1[i];
        Wh1t[k * GN + g] = Whh1[i];
    }
    for (int i = tid; i < GN; i += NTHR) {
        b0[i] = bih0[i] + bhh0[i];
        b1[i] = bih1[i] + bhh1[i];
    }
    if (tid < HN) wl[tid] = Wlin[tid];
    if (tid == 0) wl[HN] = blin[0];
    for (int i = tid; i < HN * EPAD; i += NTHR) { h0d[i] = 0ULL; h1d[i] = 0ULL; }

    // ---- thread roles ----
    const int gg4 = (tid % 50) * 4;   // GEMM: 4 consecutive gates   (tid < 200)
    const int eb  = (tid / 50) * 4;   // GEMM: 4 elems
    const int aj  = tid % 50;         // ACT: hidden unit j          (tid < 200)
    const int ae  = (tid / 50) * 4;   // ACT: 4 elems
    const int pxd = tid & 7;          // x prefetch (tid < 128)
    const int pxe = tid >> 3;

    float c0r[4] = {0.f, 0.f, 0.f, 0.f};
    float c1r[4] = {0.f, 0.f, 0.f, 0.f};

    const float* xg = x + ((size_t)(cta * EN + pxe) * TN) * DN + pxd;
    float xv = 0.f;
    if (tid < 128) xv = xg[0];

    for (int t = 0; t < TN; ++t) {
        // stage x[t] (prefetched last iter), issue prefetch of x[t+1]
        if (tid < 128) {
            xdu[pxd * EPAD + pxe] = dup2(xv);
            if (t + 1 < TN) xv = xg[(size_t)(t + 1) * DN];
        }
        __syncthreads();

        // ---------------- layer 0 gate GEMM ----------------
        if (tid < 200) {
            ull a00, a01, a02, a03, a10, a11, a12, a13;
            {
                const ull bp0 = pack2(b0[gg4],     b0[gg4 + 1]);
                const ull bp1 = pack2(b0[gg4 + 2], b0[gg4 + 3]);
                a00 = a01 = a02 = a03 = bp0;
                a10 = a11 = a12 = a13 = bp1;
            }
            gemm_acc<DN, DN>(Wi0t, xdu, gg4, eb, a00, a01, a02, a03, a10, a11, a12, a13);
            gemm_acc<HN, 5>(Wh0t, h0d, gg4, eb, a00, a01, a02, a03, a10, a11, a12, a13);
            {
                const float2 p0 = unpk2(a00), q0 = unpk2(a10);
                const float2 p1 = unpk2(a01), q1 = unpk2(a11);
                const float2 p2 = unpk2(a02), q2 = unpk2(a12);
                const float2 p3 = unpk2(a03), q3 = unpk2(a13);
                *reinterpret_cast<float4*>(&gates[(eb + 0) * GN + gg4]) = make_float4(p0.x, p0.y, q0.x, q0.y);
                *reinterpret_cast<float4*>(&gates[(eb + 1) * GN + gg4]) = make_float4(p1.x, p1.y, q1.x, q1.y);
                *reinterpret_cast<float4*>(&gates[(eb + 2) * GN + gg4]) = make_float4(p2.x, p2.y, q2.x, q2.y);
                *reinterpret_cast<float4*>(&gates[(eb + 3) * GN + gg4]) = make_float4(p3.x, p3.y, q3.x, q3.y);
            }
        }
        __syncthreads();

        // ---------------- layer 0 activations ----------------
        if (tid < 200) {
#pragma unroll
            for (int m = 0; m < 4; ++m) {
                const float* gp = gates + (ae + m) * GN + aj;
                const float i_ = sigf(gp[0]);
                const float f_ = sigf(gp[50]);
                const float g_ = tanhx(gp[100]);
                const float o_ = sigf(gp[150]);
                const float c  = fmaf(f_, c0r[m], i_ * g_);
                c0r[m] = c;
                h0d[aj * EPAD + ae + m] = dup2(o_ * tanhx(c));
            }
        }
        __syncthreads();

        // ---------------- layer 1 gate GEMM ----------------
        if (tid < 200) {
            ull a00, a01, a02, a03, a10, a11, a12, a13;
            {
                const ull bp0 = pack2(b1[gg4],     b1[gg4 + 1]);
                const ull bp1 = pack2(b1[gg4 + 2], b1[gg4 + 3]);
                a00 = a01 = a02 = a03 = bp0;
                a10 = a11 = a12 = a13 = bp1;
            }
            gemm_acc<HN, 5>(Wi1t, h0d, gg4, eb, a00, a01, a02, a03, a10, a11, a12, a13);
            gemm_acc<HN, 5>(Wh1t, h1d, gg4, eb, a00, a01, a02, a03, a10, a11, a12, a13);
            {
                const float2 p0 = unpk2(a00), q0 = unpk2(a10);
                const float2 p1 = unpk2(a01), q1 = unpk2(a11);
                const float2 p2 = unpk2(a02), q2 = unpk2(a12);
                const float2 p3 = unpk2(a03), q3 = unpk2(a13);
                *reinterpret_cast<float4*>(&gates[(eb + 0) * GN + gg4]) = make_float4(p0.x, p0.y, q0.x, q0.y);
                *reinterpret_cast<float4*>(&gates[(eb + 1) * GN + gg4]) = make_float4(p1.x, p1.y, q1.x, q1.y);
                *reinterpret_cast<float4*>(&gates[(eb + 2) * GN + gg4]) = make_float4(p2.x, p2.y, q2.x, q2.y);
                *reinterpret_cast<float4*>(&gates[(eb + 3) * GN + gg4]) = make_float4(p3.x, p3.y, q3.x, q3.y);
            }
        }
        __syncthreads();

        // ---------------- layer 1 activations ----------------
        if (tid < 200) {
#pragma unroll
            for (int m = 0; m < 4; ++m) {
                const float* gp = gates + (ae + m) * GN + aj;
                const float i_ = sigf(gp[0]);
                const float f_ = sigf(gp[50]);
                const float g_ = tanhx(gp[100]);
                const float o_ = sigf(gp[150]);
                const float c  = fmaf(f_, c1r[m], i_ * g_);
                c1r[m] = c;
                h1d[aj * EPAD + ae + m] = dup2(o_ * tanhx(c));
            }
        }
        __syncthreads();
    }

    // ---------------- linear head on last h1 ----------------
    if (tid < EN) {
        float acc = wl[HN];   // blin
#pragma unroll 10
        for (int j = 0; j < HN; ++j)
            acc = fmaf(unpk2(h1d[j * EPAD + tid]).x, wl[j], acc);
        out[cta * EN + tid] = acc;
    }
}

extern "C" void kernel_launch(void* const* d_in, const int* in_sizes, int n_in,
                              void* d_out, int out_size)
{
    const float* x    = (const float*)d_in[0];
    const float* Wih0 = (const float*)d_in[1];
    const float* Whh0 = (const float*)d_in[2];
    const float* bih0 = (const float*)d_in[3];
    const float* bhh0 = (const float*)d_in[4];
    const float* Wih1 = (const float*)d_in[5];
    const float* Whh1 = (const float*)d_in[6];
    const float* bih1 = (const float*)d_in[7];
    const float* bhh1 = (const float*)d_in[8];
    const float* Wlin = (const float*)d_in[9];
    const float* blin = (const float*)d_in[10];
    float* out = (float*)d_out;

    cudaFuncSetAttribute(lstm_fused_kernel,
                         cudaFuncAttributeMaxDynamicSharedMemorySize, SMEM_BYTES);
    lstm_fused_kernel<<<NCTA, NTHR, SMEM_BYTES>>>(
        x, Wih0, Whh0, bih0, bhh0, Wih1, Whh1, bih1, bhh1, Wlin, blin, out);
}

// round 2
// speedup vs baseline: 1.1409x; 1.1409x over previous
#include <cuda_runtime.h>

// ---------------- problem constants ----------------
#define HN   50
#define GN   200
#define DN   8
#define BN   2048
#define TN   512
#define EN   16          // batch elems per CTA
#define NCTA (BN/EN)     // 128
#define NTHR 224         // 7 warps
#define WS   112         // ull stride per k-row of a pair-packed weight matrix

typedef unsigned long long ull;

// ---- SMEM layout (ull indices) ----
#define H0_OFF   0        // [2][50][16] double-buffered h (layer 0), elem-pair packed
#define H1_OFF   1600     // [2][50][16]
#define X2_OFF   3200     // [2][8][16]
#define WX_OFF   3456     // Wih0 pair-packed [8][112]
#define W0_OFF   4352     // Whh0 [50][112]
#define W1I_OFF  9952     // Wih1 [50][112]
#define W1H_OFF  15552    // Whh1 [50][112]
#define BB_OFF   21152    // biases: b_if0[56], b_go0[56], b_if1[56], b_go1[56]
#define WL_OFF   21376    // head weights (floats, 51 used)
#define TOT_ULL  21408
#define SMEM_BYTES (TOT_ULL*8)   // 171264

// ---------------- f32x2 helpers ----------------
__device__ __forceinline__ ull pack2(float a, float b) {
    ull r; asm("mov.b64 %0, {%1, %2};" : "=l"(r) : "f"(a), "f"(b)); return r;
}
__device__ __forceinline__ ull dup2(float a) { return pack2(a, a); }
__device__ __forceinline__ void fma2(ull& d, ull a, ull b) {
    asm("fma.rn.f32x2 %0, %1, %2, %0;" : "+l"(d) : "l"(a), "l"(b));
}
__device__ __forceinline__ float2 unpk2(ull v) {
    float2 f; asm("mov.b64 {%0, %1}, %2;" : "=f"(f.x), "=f"(f.y) : "l"(v)); return f;
}
__device__ __forceinline__ float sigf(float v) {
    return __fdividef(1.f, 1.f + __expf(-v));
}
__device__ __forceinline__ float tanhx(float v) {
    return fmaf(2.f, __fdividef(1.f, 1.f + __expf(-2.f * v)), -1.f);
}

// gate GEMM block: acc[0..3] = (i,f) pairs for elems e0..e3, acc[4..7] = (g,o) pairs
template<int KK, int UN>
__device__ __forceinline__ void gemm_blk(const ull* __restrict__ Wp,   // [KK][WS]
                                         const ull* __restrict__ hp,   // row k at hp + k*16 (pre-offset by epg*4)
                                         int j, ull* acc)
{
#pragma unroll UN
    for (int k = 0; k < KK; ++k) {
        const ull wif = Wp[k * WS + j];            // LDS.64, warp-dedup'd -> 1 wf
        const ull wgo = Wp[k * WS + 56 + j];       // 1 wf
        const ulonglong2 hA = *reinterpret_cast<const ulonglong2*>(hp + k * 16);     // elems e0,e1
        const ulonglong2 hB = *reinterpret_cast<const ulonglong2*>(hp + k * 16 + 2); // elems e2,e3
        fma2(acc[0], wif, hA.x); fma2(acc[4], wgo, hA.x);
        fma2(acc[1], wif, hA.y); fma2(acc[5], wgo, hA.y);
        fma2(acc[2], wif, hB.x); fma2(acc[6], wgo, hB.x);
        fma2(acc[3], wif, hB.y); fma2(acc[7], wgo, hB.y);
    }
}

__device__ __forceinline__ float act_one(ull aif, ull ago, float& c) {
    const float2 vif = unpk2(aif);
    const float2 vgo = unpk2(ago);
    const float i_ = sigf(vif.x);
    const float f_ = sigf(vif.y);
    const float g_ = tanhx(vgo.x);
    const float o_ = sigf(vgo.y);
    c = fmaf(f_, c, i_ * g_);
    return o_ * tanhx(c);
}

__global__ void __launch_bounds__(NTHR, 1)
lstm_fused_kernel(const float* __restrict__ x,
                  const float* __restrict__ Wih0, const float* __restrict__ Whh0,
                  const float* __restrict__ bih0, const float* __restrict__ bhh0,
                  const float* __restrict__ Wih1, const float* __restrict__ Whh1,
                  const float* __restrict__ bih1, const float* __restrict__ bhh1,
                  const float* __restrict__ Wlin, const float* __restrict__ blin,
                  float* __restrict__ out)
{
    extern __shared__ ull sm[];
    ull* h0  = sm + H0_OFF;
    ull* h1  = sm + H1_OFF;
    ull* x2  = sm + X2_OFF;
    ull* Wx  = sm + WX_OFF;
    ull* W0  = sm + W0_OFF;
    ull* W1i = sm + W1I_OFF;
    ull* W1h = sm + W1H_OFF;
    ull* bb  = sm + BB_OFF;
    float* wl = reinterpret_cast<float*>(sm + WL_OFF);

    const int tid  = threadIdx.x;
    const int cta  = blockIdx.x;
    const int lane = tid & 31;
    const int wid  = tid >> 5;
    const int j    = wid * 8 + (lane & 7);   // hidden unit (valid if < 50)
    const int epg  = lane >> 3;              // elem group (0..3)
    const int e0   = epg * 4;

    // ---- stage weights (pair-packed, transposed to [k][pair][j]) ----
    for (int i = tid; i < HN * HN; i += NTHR) {
        int k = i / HN, jj = i % HN;
        W0 [k * WS + jj]      = pack2(Whh0[jj * HN + k],          Whh0[(jj + 50) * HN + k]);
        W0 [k * WS + 56 + jj] = pack2(Whh0[(jj + 100) * HN + k],  Whh0[(jj + 150) * HN + k]);
        W1i[k * WS + jj]      = pack2(Wih1[jj * HN + k],          Wih1[(jj + 50) * HN + k]);
        W1i[k * WS + 56 + jj] = pack2(Wih1[(jj + 100) * HN + k],  Wih1[(jj + 150) * HN + k]);
        W1h[k * WS + jj]      = pack2(Whh1[jj * HN + k],          Whh1[(jj + 50) * HN + k]);
        W1h[k * WS + 56 + jj] = pack2(Whh1[(jj + 100) * HN + k],  Whh1[(jj + 150) * HN + k]);
    }
    for (int i = tid; i < DN * HN; i += NTHR) {
        int k = i / HN, jj = i % HN;
        Wx[k * WS + jj]      = pack2(Wih0[jj * DN + k],           Wih0[(jj + 50) * DN + k]);
        Wx[k * WS + 56 + jj] = pack2(Wih0[(jj + 100) * DN + k],   Wih0[(jj + 150) * DN + k]);
    }
    for (int i = tid; i < HN; i += NTHR) {
        bb[i]       = pack2(bih0[i]       + bhh0[i],       bih0[i + 50]  + bhh0[i + 50]);
        bb[56 + i]  = pack2(bih0[i + 100] + bhh0[i + 100], bih0[i + 150] + bhh0[i + 150]);
        bb[112 + i] = pack2(bih1[i]       + bhh1[i],       bih1[i + 50]  + bhh1[i + 50]);
        bb[168 + i] = pack2(bih1[i + 100] + bhh1[i + 100], bih1[i + 150] + bhh1[i + 150]);
    }
    if (tid < HN) wl[tid] = Wlin[tid];
    if (tid == HN) wl[HN] = blin[0];
    for (int i = tid; i < 3200; i += NTHR) sm[H0_OFF + i] = 0ULL;  // zero h0,h1 (both buffers)

    // ---- x staging (128 threads: d = tid&7, e = tid>>3) ----
    const int pd = tid & 7, pe = tid >> 3;
    const float* xg = x + ((size_t)(cta * EN + pe) * TN) * DN + pd;
    float xv = 0.f;
    if (tid < 128) {
        x2[pd * 16 + pe] = dup2(xg[0]);      // t=0 into buffer 0
        xv = xg[DN];                          // prefetch t=1
    }
    __syncthreads();

    const ull bif0 = bb[j], bgo0 = bb[56 + j], bif1 = bb[112 + j], bgo1 = bb[168 + j];
    const bool on = (j < HN);
    float c0[4] = {0.f, 0.f, 0.f, 0.f};
    float c1[4] = {0.f, 0.f, 0.f, 0.f};

    for (int t = 0; t < TN; ++t) {
        const int cur = t & 1, nxt = cur ^ 1;
        ull* h0c = h0 + cur * 800; ull* h0n = h0 + nxt * 800;
        ull* h1c = h1 + cur * 800; ull* h1n = h1 + nxt * 800;

        __syncthreads();   // A: prev h writes + x[cur] visible

        ull acc[8];
        if (on) {
            acc[0] = acc[1] = acc[2] = acc[3] = bif0;
            acc[4] = acc[5] = acc[6] = acc[7] = bgo0;
            gemm_blk<DN, DN>(Wx, x2 + cur * 128 + e0, j, acc);
            gemm_blk<HN, 10>(W0, h0c + e0, j, acc);
        }
        // stage x[t+1], prefetch x[t+2]
        if (tid < 128) {
            x2[nxt * 128 + pd * 16 + pe] = dup2(xv);
            int tn = t + 2; if (tn > TN - 1) tn = TN - 1;
            xv = xg[(size_t)tn * DN];
        }
        if (on) {
            float v0 = act_one(acc[0], acc[4], c0[0]);
            float v1 = act_one(acc[1], acc[5], c0[1]);
            float v2 = act_one(acc[2], acc[6], c0[2]);
            float v3 = act_one(acc[3], acc[7], c0[3]);
            ulonglong2 s0; s0.x = dup2(v0); s0.y = dup2(v1);
            ulonglong2 s1; s1.x = dup2(v2); s1.y = dup2(v3);
            *reinterpret_cast<ulonglong2*>(h0n + j * 16 + e0)     = s0;
            *reinterpret_cast<ulonglong2*>(h0n + j * 16 + e0 + 2) = s1;
        }

        __syncthreads();   // B: h0[nxt] visible

        if (on) {
            acc[0] = acc[1] = acc[2] = acc[3] = bif1;
            acc[4] = acc[5] = acc[6] = acc[7] = bgo1;
            gemm_blk<HN, 10>(W1i, h0n + e0, j, acc);
            gemm_blk<HN, 10>(W1h, h1c + e0, j, acc);
            float v0 = act_one(acc[0], acc[4], c1[0]);
            float v1 = act_one(acc[1], acc[5], c1[1]);
            float v2 = act_one(acc[2], acc[6], c1[2]);
            float v3 = act_one(acc[3], acc[7], c1[3]);
            ulonglong2 s0; s0.x = dup2(v0); s0.y = dup2(v1);
            ulonglong2 s1; s1.x = dup2(v2); s1.y = dup2(v3);
            *reinterpret_cast<ulonglong2*>(h1n + j * 16 + e0)     = s0;
            *reinterpret_cast<ulonglong2*>(h1n + j * 16 + e0 + 2) = s1;
        }
    }

    __syncthreads();
    // final h1 is in buffer 0 (TN even). head: out = h_last @ Wlin^T + blin
    if (tid < EN) {
        float acc = wl[HN];
#pragma unroll 10
        for (int jj = 0; jj < HN; ++jj)
            acc = fmaf(*reinterpret_cast<const float*>(h1 + jj * 16 + tid), wl[jj], acc);
        out[cta * EN + tid] = acc;
    }
}

extern "C" void kernel_launch(void* const* d_in, const int* in_sizes, int n_in,
                              void* d_out, int out_size)
{
    const float* x    = (const float*)d_in[0];
    const float* Wih0 = (const float*)d_in[1];
    const float* Whh0 = (const float*)d_in[2];
    const float* bih0 = (const float*)d_in[3];
    const float* bhh0 = (const float*)d_in[4];
    const float* Wih1 = (const float*)d_in[5];
    const float* Whh1 = (const float*)d_in[6];
    const float* bih1 = (const float*)d_in[7];
    const float* bhh1 = (const float*)d_in[8];
    const float* Wlin = (const float*)d_in[9];
    const float* blin = (const float*)d_in[10];
    float* out = (float*)d_out;

    cudaFuncSetAttribute(lstm_fused_kernel,
                         cudaFuncAttributeMaxDynamicSharedMemorySize, SMEM_BYTES);
    lstm_fused_kernel<<<NCTA, NTHR, SMEM_BYTES>>>(
        x, Wih0, Whh0, bih0, bhh0, Wih1, Whh1, bih1, bhh1, Wlin, blin, out);
}

// round 4
// speedup vs baseline: 1.1718x; 1.0270x over previous
#include <cuda_runtime.h>

// ---------------- problem constants ----------------
#define HN   50
#define GN   200
#define DN   8
#define BN   2048
#define TN   512
#define EN   16          // batch elems per CTA
#define NCTA (BN/EN)     // 128
#define NTHR 224         // 7 warps
#define WS   112         // ull stride per k-row of a pair-packed weight matrix

typedef unsigned long long ull;

// ---- SMEM layout (ull indices) ----
#define H0_OFF   0        // [2][50][16] double-buffered h (layer 0), elem-dup packed
#define H1_OFF   1600     // [2][50][16]
#define X2_OFF   3200     // [2][8][16]
#define WX_OFF   3456     // Wih0 pair-packed [8][112]
#define W0_OFF   4352     // Whh0 [50][112]
#define W1I_OFF  9952     // Wih1 [50][112]
#define W1H_OFF  15552    // Whh1 [50][112]
#define BB_OFF   21152    // biases: b_if0[56], b_go0[56], b_if1[56], b_go1[56]
#define WL_OFF   21376    // head weights (floats, 51 used)
#define TOT_ULL  21408
#define SMEM_BYTES (TOT_ULL*8)   // 171264

// ---------------- f32x2 helpers ----------------
__device__ __forceinline__ ull pack2(float a, float b) {
    ull r; asm("mov.b64 %0, {%1, %2};" : "=l"(r) : "f"(a), "f"(b)); return r;
}
__device__ __forceinline__ ull dup2(float a) { return pack2(a, a); }
__device__ __forceinline__ void fma2(ull& d, ull a, ull b) {
    asm("fma.rn.f32x2 %0, %1, %2, %0;" : "+l"(d) : "l"(a), "l"(b));
}
__device__ __forceinline__ float2 unpk2(ull v) {
    float2 f; asm("mov.b64 {%0, %1}, %2;" : "=f"(f.x), "=f"(f.y) : "l"(v)); return f;
}
__device__ __forceinline__ float sigf(float v) {
    return __fdividef(1.f, 1.f + __expf(-v));
}
__device__ __forceinline__ float tanhx(float v) {
    return fmaf(2.f, __fdividef(1.f, 1.f + __expf(-2.f * v)), -1.f);
}

__device__ __forceinline__ float act_one(ull aif, ull ago, float& c) {
    const float2 vif = unpk2(aif);
    const float2 vgo = unpk2(ago);
    const float i_ = sigf(vif.x);
    const float f_ = sigf(vif.y);
    const float g_ = tanhx(vgo.x);
    const float o_ = sigf(vgo.y);
    c = fmaf(f_, c, i_ * g_);
    return o_ * tanhx(c);
}

__global__ void __launch_bounds__(NTHR, 1)
lstm_fused_kernel(const float* __restrict__ x,
                  const float* __restrict__ Wih0, const float* __restrict__ Whh0,
                  const float* __restrict__ bih0, const float* __restrict__ bhh0,
                  const float* __restrict__ Wih1, const float* __restrict__ Whh1,
                  const float* __restrict__ bih1, const float* __restrict__ bhh1,
                  const float* __restrict__ Wlin, const float* __restrict__ blin,
                  float* __restrict__ out)
{
    extern __shared__ ull sm[];
    ull* h0  = sm + H0_OFF;
    ull* h1  = sm + H1_OFF;
    ull* x2  = sm + X2_OFF;
    ull* Wx  = sm + WX_OFF;
    ull* W0  = sm + W0_OFF;
    ull* W1i = sm + W1I_OFF;
    ull* W1h = sm + W1H_OFF;
    ull* bb  = sm + BB_OFF;
    float* wl = reinterpret_cast<float*>(sm + WL_OFF);

    const int tid  = threadIdx.x;
    const int cta  = blockIdx.x;
    const int lane = tid & 31;
    const int wid  = tid >> 5;
    const int j    = wid * 8 + (lane & 7);   // hidden unit (valid if < 50)
    const int e0   = (lane >> 3) * 4;        // first of this thread's 4 elems

    // ---- stage weights (pair-packed, transposed to [k][pair][j]) ----
    for (int i = tid; i < HN * HN; i += NTHR) {
        int k = i / HN, jj = i % HN;
        W0 [k * WS + jj]      = pack2(Whh0[jj * HN + k],          Whh0[(jj + 50) * HN + k]);
        W0 [k * WS + 56 + jj] = pack2(Whh0[(jj + 100) * HN + k],  Whh0[(jj + 150) * HN + k]);
        W1i[k * WS + jj]      = pack2(Wih1[jj * HN + k],          Wih1[(jj + 50) * HN + k]);
        W1i[k * WS + 56 + jj] = pack2(Wih1[(jj + 100) * HN + k],  Wih1[(jj + 150) * HN + k]);
        W1h[k * WS + jj]      = pack2(Whh1[jj * HN + k],          Whh1[(jj + 50) * HN + k]);
        W1h[k * WS + 56 + jj] = pack2(Whh1[(jj + 100) * HN + k],  Whh1[(jj + 150) * HN + k]);
    }
    for (int i = tid; i < DN * HN; i += NTHR) {
        int k = i / HN, jj = i % HN;
        Wx[k * WS + jj]      = pack2(Wih0[jj * DN + k],           Wih0[(jj + 50) * DN + k]);
        Wx[k * WS + 56 + jj] = pack2(Wih0[(jj + 100) * DN + k],   Wih0[(jj + 150) * DN + k]);
    }
    for (int i = tid; i < HN; i += NTHR) {
        bb[i]       = pack2(bih0[i]       + bhh0[i],       bih0[i + 50]  + bhh0[i + 50]);
        bb[56 + i]  = pack2(bih0[i + 100] + bhh0[i + 100], bih0[i + 150] + bhh0[i + 150]);
        bb[112 + i] = pack2(bih1[i]       + bhh1[i],       bih1[i + 50]  + bhh1[i + 50]);
        bb[168 + i] = pack2(bih1[i + 100] + bhh1[i + 100], bih1[i + 150] + bhh1[i + 150]);
    }
    if (tid < HN) wl[tid] = Wlin[tid];
    if (tid == HN) wl[HN] = blin[0];
    for (int i = tid; i < 3200; i += NTHR) sm[H0_OFF + i] = 0ULL;  // zero h0,h1 (both buffers)

    // ---- x staging (128 threads: d = tid&7, e = tid>>3) ----
    const int pd = tid & 7, pe = tid >> 3;
    const float* xg = x + ((size_t)(cta * EN + pe) * TN) * DN + pd;
    float xv = 0.f;
    if (tid < 128) {
        x2[pd * 16 + pe] = dup2(xg[0]);      // x[0] into buffer 0
        xv = xg[DN];                          // prefetch x[1]
    }

    __syncthreads();   // *** staging (incl. bb) must be visible before register loads ***

    const ull bif0 = bb[j], bgo0 = bb[56 + j], bif1 = bb[112 + j], bgo1 = bb[168 + j];
    const bool on = (j < HN);
    float c0[4] = {0.f, 0.f, 0.f, 0.f};
    float c1[4] = {0.f, 0.f, 0.f, 0.f};

    // Pipelined phases: phase p computes layer0(step p) and layer1(step p-1).
    for (int p = 0; p <= TN; ++p) {
        const int pb = p & 1, qb = pb ^ 1;   // qb = (p-1)&1
        const ull* h0p = h0 + qb * 800 + e0; // h0[p-1]
        const ull* h1p = h1 + pb * 800 + e0; // h1[p-2]
        ull* h0w = h0 + pb * 800;            // h0[p]
        ull* h1w = h1 + qb * 800;            // h1[p-1]

        __syncthreads();   // h0[p-1], h1[p-2] writes + x[p] staging visible

        ull a0[8], a1[8];
        if (on) {
            a0[0] = a0[1] = a0[2] = a0[3] = bif0;
            a0[4] = a0[5] = a0[6] = a0[7] = bgo0;
            a1[0] = a1[1] = a1[2] = a1[3] = bif1;
            a1[4] = a1[5] = a1[6] = a1[7] = bgo1;

            // fused K=50: h0[p-1] feeds BOTH layer0-recurrent (a0) and layer1-input (a1)
#pragma unroll 5
            for (int k = 0; k < HN; ++k) {
                const ull w0if = W0 [k * WS + j];
                const ull w0go = W0 [k * WS + 56 + j];
                const ull w1if = W1i[k * WS + j];
                const ull w1go = W1i[k * WS + 56 + j];
                const ulonglong2 hA = *reinterpret_cast<const ulonglong2*>(h0p + k * 16);
                const ulonglong2 hB = *reinterpret_cast<const ulonglong2*>(h0p + k * 16 + 2);
                fma2(a0[0], w0if, hA.x); fma2(a0[4], w0go, hA.x);
                fma2(a1[0], w1if, hA.x); fma2(a1[4], w1go, hA.x);
                fma2(a0[1], w0if, hA.y); fma2(a0[5], w0go, hA.y);
                fma2(a1[1], w1if, hA.y); fma2(a1[5], w1go, hA.y);
                fma2(a0[2], w0if, hB.x); fma2(a0[6], w0go, hB.x);
                fma2(a1[2], w1if, hB.x); fma2(a1[6], w1go, hB.x);
                fma2(a0[3], w0if, hB.y); fma2(a0[7], w0go, hB.y);
                fma2(a1[3], w1if, hB.y); fma2(a1[7], w1go, hB.y);
            }
            // layer1 recurrent: h1[p-2]
#pragma unroll 5
            for (int k = 0; k < HN; ++k) {
                const ull wif = W1h[k * WS + j];
                const ull wgo = W1h[k * WS + 56 + j];
                const ulonglong2 hA = *reinterpret_cast<const ulonglong2*>(h1p + k * 16);
                const ulonglong2 hB = *reinterpret_cast<const ulonglong2*>(h1p + k * 16 + 2);
                fma2(a1[0], wif, hA.x); fma2(a1[4], wgo, hA.x);
                fma2(a1[1], wif, hA.y); fma2(a1[5], wgo, hA.y);
                fma2(a1[2], wif, hB.x); fma2(a1[6], wgo, hB.x);
                fma2(a1[3], wif, hB.y); fma2(a1[7], wgo, hB.y);
            }
            // layer0 input: x[p]
            const ull* xp = x2 + pb * 128 + e0;
#pragma unroll
            for (int k = 0; k < DN; ++k) {
                const ull wif = Wx[k * WS + j];
                const ull wgo = Wx[k * WS + 56 + j];
                const ulonglong2 hA = *reinterpret_cast<const ulonglong2*>(xp + k * 16);
                const ulonglong2 hB = *reinterpret_cast<const ulonglong2*>(xp + k * 16 + 2);
                fma2(a0[0], wif, hA.x); fma2(a0[4], wgo, hA.x);
                fma2(a0[1], wif, hA.y); fma2(a0[5], wgo, hA.y);
                fma2(a0[2], wif, hB.x); fma2(a0[6], wgo, hB.x);
                fma2(a0[3], wif, hB.y); fma2(a0[7], wgo, hB.y);
            }
        }

        // stage x[p+1] into buf (p+1)&1, prefetch x[p+2]
        if (tid < 128) {
            x2[qb * 128 + pd * 16 + pe] = dup2(xv);
            int tn = p + 2; if (tn > TN - 1) tn = TN - 1;
            xv = xg[(size_t)tn * DN];
        }

        if (on && p < TN) {    // layer0(p) activations -> h0[p]
            float v0 = act_one(a0[0], a0[4], c0[0]);
            float v1 = act_one(a0[1], a0[5], c0[1]);
            float v2 = act_one(a0[2], a0[6], c0[2]);
            float v3 = act_one(a0[3], a0[7], c0[3]);
            ulonglong2 s0; s0.x = dup2(v0); s0.y = dup2(v1);
            ulonglong2 s1; s1.x = dup2(v2); s1.y = dup2(v3);
            *reinterpret_cast<ulonglong2*>(h0w + j * 16 + e0)     = s0;
            *reinterpret_cast<ulonglong2*>(h0w + j * 16 + e0 + 2) = s1;
        }
        if (on && p > 0) {     // layer1(p-1) activations -> h1[p-1]
            float v0 = act_one(a1[0], a1[4], c1[0]);
            float v1 = act_one(a1[1], a1[5], c1[1]);
            float v2 = act_one(a1[2], a1[6], c1[2]);
            float v3 = act_one(a1[3], a1[7], c1[3]);
            ulonglong2 s0; s0.x = dup2(v0); s0.y = dup2(v1);
            ulonglong2 s1; s1.x = dup2(v2); s1.y = dup2(v3);
            *reinterpret_cast<ulonglong2*>(h1w + j * 16 + e0)     = s0;
            *reinterpret_cast<ulonglong2*>(h1w + j * 16 + e0 + 2) = s1;
        }
    }

    __syncthreads();
    // final h1[TN-1] lives in buffer (TN-1)&1 = 1
    if (tid < EN) {
        float acc = wl[HN];
#pragma unroll 10
        for (int jj = 0; jj < HN; ++jj)
            acc = fmaf(*reinterpret_cast<const float*>(h1 + 800 + jj * 16 + tid), wl[jj], acc);
        out[cta * EN + tid] = acc;
    }
}

extern "C" void kernel_launch(void* const* d_in, const int* in_sizes, int n_in,
                              void* d_out, int out_size)
{
    const float* x    = (const float*)d_in[0];
    const float* Wih0 = (const float*)d_in[1];
    const float* Whh0 = (const float*)d_in[2];
    const float* bih0 = (const float*)d_in[3];
    const float* bhh0 = (const float*)d_in[4];
    const float* Wih1 = (const float*)d_in[5];
    const float* Whh1 = (const float*)d_in[6];
    const float* bih1 = (const float*)d_in[7];
    const float* bhh1 = (const float*)d_in[8];
    const float* Wlin = (const float*)d_in[9];
    const float* blin = (const float*)d_in[10];
    float* out = (float*)d_out;

    cudaFuncSetAttribute(lstm_fused_kernel,
                         cudaFuncAttributeMaxDynamicSharedMemorySize, SMEM_BYTES);
    lstm_fused_kernel<<<NCTA, NTHR, SMEM_BYTES>>>(
        x, Wih0, Whh0, bih0, bhh0, Wih1, Whh1, bih1, bhh1, Wlin, blin, out);
}